// round 13
// baseline (speedup 1.0000x reference)
#include <cuda_runtime.h>

#define BS    256
#define FTN   8
#define ATN   264          // BS + FTN
#define NDIM  512
#define NBLK  8448         // BS*ATN warps / 8 warps per block

// Accumulators + completion counter (zeroed at module load; the final block
// resets them after consuming, so every graph replay starts clean).
__device__ float g_rowsum[BS];   // sum_a exp(L[b,a])
__device__ float g_colsum[BS];   // sum_b exp(L[b,a]), a < 256
__device__ float g_diagsum;      // sum_b L[b,b]
__device__ int   g_count;        // blocks completed

__device__ __forceinline__ float4 ldcs4(const float4* p) {
    float4 v;
    asm volatile("ld.global.cs.v4.f32 {%0,%1,%2,%3}, [%4];"
                 : "=f"(v.x), "=f"(v.y), "=f"(v.z), "=f"(v.w) : "l"(p));
    return v;
}
__device__ __forceinline__ float4 ldnc4(const float4* p) {
    float4 v;
    asm volatile("ld.global.nc.v4.f32 {%0,%1,%2,%3}, [%4];"
                 : "=f"(v.x), "=f"(v.y), "=f"(v.z), "=f"(v.w) : "l"(p));
    return v;
}
__device__ __forceinline__ float ldcg1(const float* p) {
    float v;
    asm volatile("ld.global.cg.f32 %0, [%1];" : "=f"(v) : "l"(p));
    return v;
}

__device__ __forceinline__ void acc3(const float4& x, const float4& t,
                                     float& dot, float& in2, float& tn2)
{
    dot += x.x * t.x + x.y * t.y + x.z * t.z + x.w * t.w;
    in2 += x.x * x.x + x.y * x.y + x.z * x.z + x.w * x.w;
    tn2 += t.x * t.x + t.y * t.y + t.z * t.z + t.w * t.w;
}

// ---------------------------------------------------------------------------
// SINGLE kernel.
// Phase 1 (R7's measured-best streaming order): warp w -> gwarp = blockIdx*8+w,
//   b = gwarp/ATN, a = gwarp%ATN. 8 front-batched LDG.128; image row-major
//   (perfect DRAM streaming), evict-first. lane 0 accumulates exp-sums via L2
//   atomics (|L| <= e, so no max subtraction needed) and fences.
// Phase 2 (last-ticket block, NO spin): once a block draws ticket NBLK-1,
//   every other block's fenced atomics are L2-visible. It computes
//   loss = (sum log rowsum + sum log colsum - 2*diagsum)/512, writes out,
//   and resets all device state for the next graph replay.
// ---------------------------------------------------------------------------
__global__ __launch_bounds__(256) void cl_fused_kernel(
    const float* __restrict__ img,
    const float* __restrict__ rand_t,
    const float* __restrict__ false_t,
    const float* __restrict__ logit_scale,
    float* __restrict__ out)
{
    __shared__ int   s_ticket;
    __shared__ float sd[256];

    int wid   = threadIdx.x >> 5;
    int lane  = threadIdx.x & 31;
    int gwarp = blockIdx.x * 8 + wid;

    // ---------------- Phase 1: dot + exp-accumulate ----------------
    {
        int b = gwarp / ATN;
        int a = gwarp - b * ATN;

        const float4* ip = (const float4*)(img + (size_t)gwarp * NDIM);
        const float*  tbase = (a < BS)
            ? (rand_t + (size_t)a * NDIM)
            : (false_t + ((size_t)b * FTN + (a - BS)) * NDIM);
        const float4* tp = (const float4*)tbase;

        float4 x0 = ldcs4(ip + lane);
        float4 x1 = ldcs4(ip + lane + 32);
        float4 x2 = ldcs4(ip + lane + 64);
        float4 x3 = ldcs4(ip + lane + 96);
        float4 t0 = ldnc4(tp + lane);
        float4 t1 = ldnc4(tp + lane + 32);
        float4 t2 = ldnc4(tp + lane + 64);
        float4 t3 = ldnc4(tp + lane + 96);

        float dot = 0.f, in2 = 0.f, tn2 = 0.f;
        acc3(x0, t0, dot, in2, tn2);
        acc3(x1, t1, dot, in2, tn2);
        acc3(x2, t2, dot, in2, tn2);
        acc3(x3, t3, dot, in2, tn2);

        #pragma unroll
        for (int o = 16; o > 0; o >>= 1) {
            dot += __shfl_xor_sync(0xffffffffu, dot, o);
            in2 += __shfl_xor_sync(0xffffffffu, in2, o);
            tn2 += __shfl_xor_sync(0xffffffffu, tn2, o);
        }
        if (lane == 0) {
            float scale = expf(logit_scale[0]);
            float lg = scale * dot * rsqrtf(in2 * tn2);   // |lg| <= scale
            float e  = expf(lg);
            atomicAdd(&g_rowsum[b], e);
            if (a < BS) atomicAdd(&g_colsum[a], e);
            if (a == b) atomicAdd(&g_diagsum, lg);
            __threadfence();            // release this warp's atomics (8/block)
        }
    }

    // ---------------- Ticket (no spin) ----------------
    __syncthreads();                    // joins the lane-0 fences
    if (threadIdx.x == 0)
        s_ticket = atomicAdd(&g_count, 1);
    __syncthreads();
    if (s_ticket != NBLK - 1) return;

    // ---------------- Phase 2: final reduction in the last block ------------
    int t = threadIdx.x;
    float rs = ldcg1(&g_rowsum[t]);     // L2-direct: atomics live at L2
    float cs = ldcg1(&g_colsum[t]);
    sd[t] = logf(rs) + logf(cs);
    __syncthreads();
    #pragma unroll
    for (int s = 128; s > 0; s >>= 1) {
        if (t < s) sd[t] += sd[t + s];
        __syncthreads();
    }
    if (t == 0) {
        float ds = ldcg1(&g_diagsum);
        out[0] = (sd[0] - 2.0f * ds) * (1.0f / (2.0f * BS));
        g_diagsum = 0.0f;
        g_count   = 0;
    }
    // reset accumulators for next replay (values already consumed)
    g_rowsum[t] = 0.0f;
    g_colsum[t] = 0.0f;
}

extern "C" void kernel_launch(void* const* d_in, const int* in_sizes, int n_in,
                              void* d_out, int out_size)
{
    const float* img     = (const float*)d_in[0];  // [256, 264, 512]
    const float* rand_t  = (const float*)d_in[1];  // [256, 512]
    const float* false_t = (const float*)d_in[2];  // [2048, 512]
    const float* lscale  = (const float*)d_in[3];  // [1]
    float* out = (float*)d_out;

    cl_fused_kernel<<<NBLK, 256>>>(img, rand_t, false_t, lscale, out);
}

// round 14
// speedup vs baseline: 1.9623x; 1.9623x over previous
#include <cuda_runtime.h>

#define BS   256
#define FTN  8
#define ATN  264   // BS + FTN
#define NDIM 512
#define TB   8     // b rows per block
#define TA   8     // a cols per block

#define NBG  (BS / TB)          // 32 b-groups
#define NAG  (ATN / TA)         // 33 a-groups (last one = false region)

// Scratch (no allocations allowed)
__device__ float g_logits[BS * ATN];
__device__ float g_logitsT[BS * BS];   // [a*BS + b], a < 256

__device__ __forceinline__ float4 ldcs4(const float4* p) {
    float4 v;
    asm volatile("ld.global.cs.v4.f32 {%0,%1,%2,%3}, [%4];"
                 : "=f"(v.x), "=f"(v.y), "=f"(v.z), "=f"(v.w) : "l"(p));
    return v;
}
__device__ __forceinline__ float4 ldnc4(const float4* p) {
    float4 v;
    asm volatile("ld.global.nc.v4.f32 {%0,%1,%2,%3}, [%4];"
                 : "=f"(v.x), "=f"(v.y), "=f"(v.z), "=f"(v.w) : "l"(p));
    return v;
}

__device__ __forceinline__ float wsum(float v) {
    #pragma unroll
    for (int o = 16; o > 0; o >>= 1) v += __shfl_xor_sync(0xffffffffu, v, o);
    return v;
}

// ---------------------------------------------------------------------------
// Kernel 1: 2-D tiled dot kernel.
//  Square blocks (ag<32): 8b x 8a tile. Text tile rand[a0:a0+8] (16 KB) staged
//    in smem once, reused by 8 b-warps (text L2 traffic /8). Image reads are
//    8 contiguous 16 KB chunks per warp — perfect DRAM streaming preserved.
//  False blocks (ag==32): warp wid -> b=b0+wid, loops j=0..7 over false pairs.
//  No atomics, no fences. Logits stored row-major + transposed (square).
// ---------------------------------------------------------------------------
__global__ __launch_bounds__(256) void cl_dot_kernel(
    const float* __restrict__ img,
    const float* __restrict__ rand_t,
    const float* __restrict__ false_t,
    const float* __restrict__ logit_scale,
    float* __restrict__ out)
{
    __shared__ float4 s_text[TA * NDIM / 4];   // 16 KB: 8 text rows
    __shared__ float  s_tn2[TA];               // 8 text norms

    int wid  = threadIdx.x >> 5;
    int lane = threadIdx.x & 31;
    int bg   = blockIdx.x / NAG;               // b-group (memory-major)
    int ag   = blockIdx.x - bg * NAG;          // a-group
    int b0   = bg * TB;
    int a0   = ag * TA;
    int b    = b0 + wid;

    if (blockIdx.x == 0 && threadIdx.x == 0) out[0] = 0.0f;

    float scale = expf(logit_scale[0]);

    if (ag < NAG - 1) {
        // ---------------- square tile ----------------
        // Stage 8 text rows (1024 float4) cooperatively: 4 per thread.
        const float4* tg = (const float4*)(rand_t + (size_t)a0 * NDIM);
        #pragma unroll
        for (int k = 0; k < 4; k++)
            s_text[threadIdx.x + 256 * k] = ldnc4(tg + threadIdx.x + 256 * k);
        __syncthreads();

        // Warp wid computes the norm of text row wid.
        {
            float tn = 0.f;
            #pragma unroll
            for (int k = 0; k < 4; k++) {
                float4 t = s_text[wid * (NDIM / 4) + lane + 32 * k];
                tn += t.x * t.x + t.y * t.y + t.z * t.z + t.w * t.w;
            }
            tn = wsum(tn);
            if (lane == 0) s_tn2[wid] = tn;
        }
        __syncthreads();

        // Each warp: 8 image rows img[b, a0+ai, :] (contiguous 16 KB stream).
        const float4* ib = (const float4*)(img + ((size_t)b * ATN + a0) * NDIM);
        float dotv[TA], in2v[TA];
        #pragma unroll
        for (int ai = 0; ai < TA; ai++) {
            const float4* ip = ib + ai * (NDIM / 4);
            float4 x0 = ldcs4(ip + lane);
            float4 x1 = ldcs4(ip + lane + 32);
            float4 x2 = ldcs4(ip + lane + 64);
            float4 x3 = ldcs4(ip + lane + 96);
            float4 t0 = s_text[ai * (NDIM / 4) + lane];
            float4 t1 = s_text[ai * (NDIM / 4) + lane + 32];
            float4 t2 = s_text[ai * (NDIM / 4) + lane + 64];
            float4 t3 = s_text[ai * (NDIM / 4) + lane + 96];
            float d = 0.f, n = 0.f;
            d += x0.x*t0.x + x0.y*t0.y + x0.z*t0.z + x0.w*t0.w;
            n += x0.x*x0.x + x0.y*x0.y + x0.z*x0.z + x0.w*x0.w;
            d += x1.x*t1.x + x1.y*t1.y + x1.z*t1.z + x1.w*t1.w;
            n += x1.x*x1.x + x1.y*x1.y + x1.z*x1.z + x1.w*x1.w;
            d += x2.x*t2.x + x2.y*t2.y + x2.z*t2.z + x2.w*t2.w;
            n += x2.x*x2.x + x2.y*x2.y + x2.z*x2.z + x2.w*x2.w;
            d += x3.x*t3.x + x3.y*t3.y + x3.z*t3.z + x3.w*t3.w;
            n += x3.x*x3.x + x3.y*x3.y + x3.z*x3.z + x3.w*x3.w;
            dotv[ai] = d;
            in2v[ai] = n;
        }
        #pragma unroll
        for (int ai = 0; ai < TA; ai++) {
            dotv[ai] = wsum(dotv[ai]);
            in2v[ai] = wsum(in2v[ai]);
        }
        if (lane == 0) {
            #pragma unroll
            for (int ai = 0; ai < TA; ai++) {
                int a = a0 + ai;
                float lg = scale * dotv[ai] * rsqrtf(in2v[ai] * s_tn2[ai]);
                g_logits[(size_t)b * ATN + a] = lg;
                g_logitsT[(size_t)a * BS + b] = lg;
            }
        }
    } else {
        // ---------------- false region: warp b, 8 sequential pairs ----------
        const float4* ib = (const float4*)(img + ((size_t)b * ATN + BS) * NDIM);
        const float4* fb = (const float4*)(false_t + (size_t)b * FTN * NDIM);
        #pragma unroll
        for (int j = 0; j < FTN; j++) {
            const float4* ip = ib + j * (NDIM / 4);
            const float4* tp = fb + j * (NDIM / 4);
            float4 x0 = ldcs4(ip + lane);
            float4 x1 = ldcs4(ip + lane + 32);
            float4 x2 = ldcs4(ip + lane + 64);
            float4 x3 = ldcs4(ip + lane + 96);
            float4 t0 = ldnc4(tp + lane);
            float4 t1 = ldnc4(tp + lane + 32);
            float4 t2 = ldnc4(tp + lane + 64);
            float4 t3 = ldnc4(tp + lane + 96);
            float d = 0.f, n = 0.f, tn = 0.f;
            d += x0.x*t0.x + x0.y*t0.y + x0.z*t0.z + x0.w*t0.w;
            n += x0.x*x0.x + x0.y*x0.y + x0.z*x0.z + x0.w*x0.w;
            tn += t0.x*t0.x + t0.y*t0.y + t0.z*t0.z + t0.w*t0.w;
            d += x1.x*t1.x + x1.y*t1.y + x1.z*t1.z + x1.w*t1.w;
            n += x1.x*x1.x + x1.y*x1.y + x1.z*x1.z + x1.w*x1.w;
            tn += t1.x*t1.x + t1.y*t1.y + t1.z*t1.z + t1.w*t1.w;
            d += x2.x*t2.x + x2.y*t2.y + x2.z*t2.z + x2.w*t2.w;
            n += x2.x*x2.x + x2.y*x2.y + x2.z*x2.z + x2.w*x2.w;
            tn += t2.x*t2.x + t2.y*t2.y + t2.z*t2.z + t2.w*t2.w;
            d += x3.x*t3.x + x3.y*t3.y + x3.z*t3.z + x3.w*t3.w;
            n += x3.x*x3.x + x3.y*x3.y + x3.z*x3.z + x3.w*x3.w;
            tn += t3.x*t3.x + t3.y*t3.y + t3.z*t3.z + t3.w*t3.w;
            d  = wsum(d);
            n  = wsum(n);
            tn = wsum(tn);
            if (lane == 0)
                g_logits[(size_t)b * ATN + BS + j] = scale * d * rsqrtf(n * tn);
        }
    }
}

// ---------------------------------------------------------------------------
// Kernel 2 (R7 form, measured): one warp per CE term, one atomic per block.
// ---------------------------------------------------------------------------
__global__ __launch_bounds__(256) void cl_lse_kernel(float* __restrict__ out)
{
    __shared__ float s_term[8];
    int gw   = (blockIdx.x * blockDim.x + threadIdx.x) >> 5;
    int wid  = threadIdx.x >> 5;
    int lane = threadIdx.x & 31;

    float v[9];
    float diag;
    if (gw < BS) {
        const float* row = g_logits + (size_t)gw * ATN;
        #pragma unroll
        for (int i = 0; i < 8; i++) v[i] = row[lane + 32 * i];
        v[8] = (lane < FTN) ? row[BS + lane] : -1e30f;
        diag = row[gw];
    } else {
        int a = gw - BS;
        const float* row = g_logitsT + (size_t)a * BS;
        #pragma unroll
        for (int i = 0; i < 8; i++) v[i] = row[lane + 32 * i];
        v[8] = -1e30f;
        diag = row[a];
    }

    float m = v[0];
    #pragma unroll
    for (int i = 1; i < 9; i++) m = fmaxf(m, v[i]);
    #pragma unroll
    for (int o = 16; o > 0; o >>= 1)
        m = fmaxf(m, __shfl_xor_sync(0xffffffffu, m, o));

    float s = 0.f;
    #pragma unroll
    for (int i = 0; i < 9; i++) s += expf(v[i] - m);
    #pragma unroll
    for (int o = 16; o > 0; o >>= 1)
        s += __shfl_xor_sync(0xffffffffu, s, o);

    if (lane == 0)
        s_term[wid] = m + logf(s) - diag;
    __syncthreads();

    if (wid == 0) {
        float t = (lane < 8) ? s_term[lane] : 0.f;
        #pragma unroll
        for (int o = 4; o > 0; o >>= 1)
            t += __shfl_xor_sync(0xffffffffu, t, o);
        if (lane == 0)
            atomicAdd(out, t * (1.0f / (2.0f * BS)));
    }
}

extern "C" void kernel_launch(void* const* d_in, const int* in_sizes, int n_in,
                              void* d_out, int out_size)
{
    const float* img     = (const float*)d_in[0];  // [256, 264, 512]
    const float* rand_t  = (const float*)d_in[1];  // [256, 512]
    const float* false_t = (const float*)d_in[2];  // [2048, 512]
    const float* lscale  = (const float*)d_in[3];  // [1]
    float* out = (float*)d_out;

    cl_dot_kernel<<<NBG * NAG, 256>>>(img, rand_t, false_t, lscale, out);
    cl_lse_kernel<<<64, 256>>>(out);
}

// round 15
// speedup vs baseline: 2.3491x; 1.1971x over previous
#include <cuda_runtime.h>

#define BS   256
#define FTN  8
#define ATN  264   // BS + FTN
#define NDIM 512
#define NBLK (BS / 8 * ATN)   // 8448 blocks: (b-group of 8) x a

// Scratch (no allocations allowed)
__device__ float g_logits[BS * ATN];
__device__ float g_logitsT[BS * BS];   // [a*BS + b], a < 256

__device__ __forceinline__ float4 ldcs4(const float4* p) {
    float4 v;
    asm volatile("ld.global.cs.v4.f32 {%0,%1,%2,%3}, [%4];"
                 : "=f"(v.x), "=f"(v.y), "=f"(v.z), "=f"(v.w) : "l"(p));
    return v;
}
__device__ __forceinline__ float4 ldnc4(const float4* p) {
    float4 v;
    asm volatile("ld.global.nc.v4.f32 {%0,%1,%2,%3}, [%4];"
                 : "=f"(v.x), "=f"(v.y), "=f"(v.z), "=f"(v.w) : "l"(p));
    return v;
}

__device__ __forceinline__ void acc3(const float4& x, const float4& t,
                                     float& dot, float& in2, float& tn2)
{
    dot += x.x * t.x + x.y * t.y + x.z * t.z + x.w * t.w;
    in2 += x.x * x.x + x.y * x.y + x.z * x.z + x.w * x.w;
    tn2 += t.x * t.x + t.y * t.y + t.z * t.z + t.w * t.w;
}

// ---------------------------------------------------------------------------
// Kernel 1: R7 per-warp shape, remapped blocks to share the text row.
//   block bx -> bg = bx/ATN, a = bx%ATN; warp wid -> b = bg*8 + wid.
//   a < 256:  rand[a] (2 KB) staged in smem ONCE per block; 8 warps reuse it
//             -> text L2 traffic /8 (138 -> 17 MB), LTS unbound.
//   a >= 256: per-warp false text row, direct loads (R7 path).
//   Concurrent blocks stream 8 sequential b-rows -> DRAM locality preserved.
// ---------------------------------------------------------------------------
__global__ __launch_bounds__(256) void cl_dot_kernel(
    const float* __restrict__ img,
    const float* __restrict__ rand_t,
    const float* __restrict__ false_t,
    const float* __restrict__ logit_scale,
    float* __restrict__ out)
{
    __shared__ float4 s_text[NDIM / 4];    // 2 KB staged text row

    int wid  = threadIdx.x >> 5;
    int lane = threadIdx.x & 31;
    int bg   = blockIdx.x / ATN;
    int a    = blockIdx.x - bg * ATN;
    int b    = bg * 8 + wid;

    if (blockIdx.x == 0 && threadIdx.x == 0) out[0] = 0.0f;

    const float4* ip = (const float4*)(img + ((size_t)b * ATN + a) * NDIM);

    float dot = 0.f, in2 = 0.f, tn2 = 0.f;

    if (a < BS) {
        // Stage text row cooperatively (threads 0..127, one float4 each).
        if (threadIdx.x < NDIM / 4)
            s_text[threadIdx.x] = ldnc4((const float4*)(rand_t + (size_t)a * NDIM)
                                        + threadIdx.x);
        __syncthreads();

        float4 x0 = ldcs4(ip + lane);
        float4 x1 = ldcs4(ip + lane + 32);
        float4 x2 = ldcs4(ip + lane + 64);
        float4 x3 = ldcs4(ip + lane + 96);
        float4 t0 = s_text[lane];
        float4 t1 = s_text[lane + 32];
        float4 t2 = s_text[lane + 64];
        float4 t3 = s_text[lane + 96];

        acc3(x0, t0, dot, in2, tn2);
        acc3(x1, t1, dot, in2, tn2);
        acc3(x2, t2, dot, in2, tn2);
        acc3(x3, t3, dot, in2, tn2);
    } else {
        const float4* tp = (const float4*)(false_t
                           + ((size_t)b * FTN + (a - BS)) * NDIM);
        float4 x0 = ldcs4(ip + lane);
        float4 x1 = ldcs4(ip + lane + 32);
        float4 x2 = ldcs4(ip + lane + 64);
        float4 x3 = ldcs4(ip + lane + 96);
        float4 t0 = ldnc4(tp + lane);
        float4 t1 = ldnc4(tp + lane + 32);
        float4 t2 = ldnc4(tp + lane + 64);
        float4 t3 = ldnc4(tp + lane + 96);

        acc3(x0, t0, dot, in2, tn2);
        acc3(x1, t1, dot, in2, tn2);
        acc3(x2, t2, dot, in2, tn2);
        acc3(x3, t3, dot, in2, tn2);
    }

    #pragma unroll
    for (int o = 16; o > 0; o >>= 1) {
        dot += __shfl_xor_sync(0xffffffffu, dot, o);
        in2 += __shfl_xor_sync(0xffffffffu, in2, o);
        tn2 += __shfl_xor_sync(0xffffffffu, tn2, o);
    }
    if (lane == 0) {
        float scale = expf(logit_scale[0]);
        float lg = scale * dot * rsqrtf(in2 * tn2);
        g_logits[(size_t)b * ATN + a] = lg;
        if (a < BS) g_logitsT[(size_t)a * BS + b] = lg;
    }
}

// ---------------------------------------------------------------------------
// Kernel 2 (R7 form, measured): one warp per CE term, one atomic per block.
// ---------------------------------------------------------------------------
__global__ __launch_bounds__(256) void cl_lse_kernel(float* __restrict__ out)
{
    __shared__ float s_term[8];
    int gw   = (blockIdx.x * blockDim.x + threadIdx.x) >> 5;
    int wid  = threadIdx.x >> 5;
    int lane = threadIdx.x & 31;

    float v[9];
    float diag;
    if (gw < BS) {
        const float* row = g_logits + (size_t)gw * ATN;
        #pragma unroll
        for (int i = 0; i < 8; i++) v[i] = row[lane + 32 * i];
        v[8] = (lane < FTN) ? row[BS + lane] : -1e30f;
        diag = row[gw];
    } else {
        int a = gw - BS;
        const float* row = g_logitsT + (size_t)a * BS;
        #pragma unroll
        for (int i = 0; i < 8; i++) v[i] = row[lane + 32 * i];
        v[8] = -1e30f;
        diag = row[a];
    }

    float m = v[0];
    #pragma unroll
    for (int i = 1; i < 9; i++) m = fmaxf(m, v[i]);
    #pragma unroll
    for (int o = 16; o > 0; o >>= 1)
        m = fmaxf(m, __shfl_xor_sync(0xffffffffu, m, o));

    float s = 0.f;
    #pragma unroll
    for (int i = 0; i < 9; i++) s += expf(v[i] - m);
    #pragma unroll
    for (int o = 16; o > 0; o >>= 1)
        s += __shfl_xor_sync(0xffffffffu, s, o);

    if (lane == 0)
        s_term[wid] = m + logf(s) - diag;
    __syncthreads();

    if (wid == 0) {
        float t = (lane < 8) ? s_term[lane] : 0.f;
        #pragma unroll
        for (int o = 4; o > 0; o >>= 1)
            t += __shfl_xor_sync(0xffffffffu, t, o);
        if (lane == 0)
            atomicAdd(out, t * (1.0f / (2.0f * BS)));
    }
}

extern "C" void kernel_launch(void* const* d_in, const int* in_sizes, int n_in,
                              void* d_out, int out_size)
{
    const float* img     = (const float*)d_in[0];  // [256, 264, 512]
    const float* rand_t  = (const float*)d_in[1];  // [256, 512]
    const float* false_t = (const float*)d_in[2];  // [2048, 512]
    const float* lscale  = (const float*)d_in[3];  // [1]
    float* out = (float*)d_out;

    cl_dot_kernel<<<NBLK, 256>>>(img, rand_t, false_t, lscale, out);
    cl_lse_kernel<<<64, 256>>>(out);
}

// round 16
// speedup vs baseline: 2.3753x; 1.0111x over previous
#include <cuda_runtime.h>

#define BS   256
#define FTN  8
#define ATN  264   // BS + FTN
#define NDIM 512

// Scratch (no allocations allowed): exp(logits) + transposed square part
__device__ float g_exp[BS * ATN];     // exp(L[b,a]), row-major
__device__ float g_expT[BS * BS];     // exp(L[b,a]) at [a*BS+b], a < 256
__device__ float g_diagL[BS];         // L[b,b] (raw logit, for the -diag term)

// Image: evict-first in L1 + 256B L2 prefetch (doubles per-request DRAM fill).
__device__ __forceinline__ float4 ldpf4(const float4* p) {
    float4 v;
    asm volatile("ld.global.L1::evict_first.L2::256B.v4.f32 {%0,%1,%2,%3}, [%4];"
                 : "=f"(v.x), "=f"(v.y), "=f"(v.z), "=f"(v.w) : "l"(p));
    return v;
}
__device__ __forceinline__ float4 ldnc4(const float4* p) {
    float4 v;
    asm volatile("ld.global.nc.v4.f32 {%0,%1,%2,%3}, [%4];"
                 : "=f"(v.x), "=f"(v.y), "=f"(v.z), "=f"(v.w) : "l"(p));
    return v;
}

__device__ __forceinline__ void acc3(const float4& x, const float4& t,
                                     float& dot, float& in2, float& tn2)
{
    dot += x.x * t.x + x.y * t.y + x.z * t.z + x.w * t.w;
    in2 += x.x * x.x + x.y * x.y + x.z * x.z + x.w * x.w;
    tn2 += t.x * t.x + t.y * t.y + t.z * t.z + t.w * t.w;
}

// ---------------------------------------------------------------------------
// Kernel 1 (R7 structure, measured best): one warp per (b, a).
//   lg = exp(logit_scale) * dot / (|img||text|);  stores exp(lg) (row + T)
//   and raw lg for the diagonal. |lg| <= e, so unnormalized exp is safe.
// ---------------------------------------------------------------------------
__global__ __launch_bounds__(256) void cl_dot_kernel(
    const float* __restrict__ img,
    const float* __restrict__ rand_t,
    const float* __restrict__ false_t,
    const float* __restrict__ logit_scale,
    float* __restrict__ out)
{
    int gwarp = (blockIdx.x * blockDim.x + threadIdx.x) >> 5;
    int lane  = threadIdx.x & 31;
    if (blockIdx.x == 0 && threadIdx.x == 0) out[0] = 0.0f;
    if (gwarp >= BS * ATN) return;

    int b = gwarp / ATN;
    int a = gwarp - b * ATN;

    const float4* ip = (const float4*)(img + (size_t)gwarp * NDIM);
    const float*  tbase = (a < BS)
        ? (rand_t + (size_t)a * NDIM)
        : (false_t + ((size_t)b * FTN + (a - BS)) * NDIM);
    const float4* tp = (const float4*)tbase;

    float4 x0 = ldpf4(ip + lane);
    float4 x1 = ldpf4(ip + lane + 32);
    float4 x2 = ldpf4(ip + lane + 64);
    float4 x3 = ldpf4(ip + lane + 96);
    float4 t0 = ldnc4(tp + lane);
    float4 t1 = ldnc4(tp + lane + 32);
    float4 t2 = ldnc4(tp + lane + 64);
    float4 t3 = ldnc4(tp + lane + 96);

    float dot = 0.f, in2 = 0.f, tn2 = 0.f;
    acc3(x0, t0, dot, in2, tn2);
    acc3(x1, t1, dot, in2, tn2);
    acc3(x2, t2, dot, in2, tn2);
    acc3(x3, t3, dot, in2, tn2);

    #pragma unroll
    for (int o = 16; o > 0; o >>= 1) {
        dot += __shfl_xor_sync(0xffffffffu, dot, o);
        in2 += __shfl_xor_sync(0xffffffffu, in2, o);
        tn2 += __shfl_xor_sync(0xffffffffu, tn2, o);
    }
    if (lane == 0) {
        float scale = expf(logit_scale[0]);
        float lg = scale * dot * rsqrtf(in2 * tn2);   // |lg| <= scale (= e)
        float e  = expf(lg);
        g_exp[gwarp] = e;
        if (a < BS) g_expT[(size_t)a * BS + b] = e;
        if (a == b) g_diagL[b] = lg;
    }
}

// ---------------------------------------------------------------------------
// Kernel 2: one warp per CE term. No max pass, no expf — just sum + log.
//   row term b:  log(sum_a exp[b,a]) - diagL[b]
//   col term a:  log(sum_b expT[a,b]) - diagL[a]
// Block-level reduction -> one atomicAdd per block.
// ---------------------------------------------------------------------------
__global__ __launch_bounds__(256) void cl_lse_kernel(float* __restrict__ out)
{
    __shared__ float s_term[8];
    int gw   = (blockIdx.x * blockDim.x + threadIdx.x) >> 5;
    int wid  = threadIdx.x >> 5;
    int lane = threadIdx.x & 31;

    float s = 0.f;
    float diag;
    if (gw < BS) {
        const float* row = g_exp + (size_t)gw * ATN;
        #pragma unroll
        for (int i = 0; i < 8; i++) s += row[lane + 32 * i];
        if (lane < FTN) s += row[BS + lane];
        diag = g_diagL[gw];
    } else {
        int a = gw - BS;
        const float* row = g_expT + (size_t)a * BS;
        #pragma unroll
        for (int i = 0; i < 8; i++) s += row[lane + 32 * i];
        diag = g_diagL[a];
    }

    #pragma unroll
    for (int o = 16; o > 0; o >>= 1)
        s += __shfl_xor_sync(0xffffffffu, s, o);

    if (lane == 0)
        s_term[wid] = logf(s) - diag;
    __syncthreads();

    if (wid == 0) {
        float t = (lane < 8) ? s_term[lane] : 0.f;
        #pragma unroll
        for (int o = 4; o > 0; o >>= 1)
            t += __shfl_xor_sync(0xffffffffu, t, o);
        if (lane == 0)
            atomicAdd(out, t * (1.0f / (2.0f * BS)));
    }
}

extern "C" void kernel_launch(void* const* d_in, const int* in_sizes, int n_in,
                              void* d_out, int out_size)
{
    const float* img     = (const float*)d_in[0];  // [256, 264, 512]
    const float* rand_t  = (const float*)d_in[1];  // [256, 512]
    const float* false_t = (const float*)d_in[2];  // [2048, 512]
    const float* lscale  = (const float*)d_in[3];  // [1]
    float* out = (float*)d_out;

    const int nwarps1 = BS * ATN;                   // 67584
    const int tpb = 256;
    const int nblocks1 = (nwarps1 * 32 + tpb - 1) / tpb;  // 8448

    cl_dot_kernel<<<nblocks1, tpb>>>(img, rand_t, false_t, lscale, out);
    cl_lse_kernel<<<64, tpb>>>(out);
}

// round 17
// speedup vs baseline: 2.3806x; 1.0022x over previous
#include <cuda_runtime.h>

#define BS   256
#define FTN  8
#define ATN  264   // BS + FTN
#define NDIM 512

// Scratch (no allocations allowed): exp(logits) + transposed square part
__device__ float g_exp[BS * ATN];     // exp(L[b,a]), row-major
__device__ float g_expT[BS * BS];     // exp(L[b,a]) at [a*BS+b], a < 256
__device__ float g_diagL[BS];         // L[b,b] (raw logit, for the -diag term)

__device__ __forceinline__ float4 ldcs4(const float4* p) {
    float4 v;
    asm volatile("ld.global.cs.v4.f32 {%0,%1,%2,%3}, [%4];"
                 : "=f"(v.x), "=f"(v.y), "=f"(v.z), "=f"(v.w) : "l"(p));
    return v;
}
__device__ __forceinline__ float4 ldnc4(const float4* p) {
    float4 v;
    asm volatile("ld.global.nc.v4.f32 {%0,%1,%2,%3}, [%4];"
                 : "=f"(v.x), "=f"(v.y), "=f"(v.z), "=f"(v.w) : "l"(p));
    return v;
}

__device__ __forceinline__ void acc3(const float4& x, const float4& t,
                                     float& dot, float& in2, float& tn2)
{
    dot += x.x * t.x + x.y * t.y + x.z * t.z + x.w * t.w;
    in2 += x.x * x.x + x.y * x.y + x.z * x.z + x.w * x.w;
    tn2 += t.x * t.x + t.y * t.y + t.z * t.z + t.w * t.w;
}

// ---------------------------------------------------------------------------
// Kernel 1 (measured-best structure): one warp per (b, a).
//   lg = exp(logit_scale) * dot / (|img||text|);  stores exp(lg) (row + T)
//   and raw lg for the diagonal. |lg| <= e, so unnormalized exp is safe.
// Ends with the PDL trigger so the secondary kernel can pre-launch.
// ---------------------------------------------------------------------------
__global__ __launch_bounds__(256) void cl_dot_kernel(
    const float* __restrict__ img,
    const float* __restrict__ rand_t,
    const float* __restrict__ false_t,
    const float* __restrict__ logit_scale,
    float* __restrict__ out)
{
    int gwarp = (blockIdx.x * blockDim.x + threadIdx.x) >> 5;  // exact: 67584 warps
    int lane  = threadIdx.x & 31;
    if (blockIdx.x == 0 && threadIdx.x == 0) out[0] = 0.0f;

    int b = gwarp / ATN;
    int a = gwarp - b * ATN;

    const float4* ip = (const float4*)(img + (size_t)gwarp * NDIM);
    const float*  tbase = (a < BS)
        ? (rand_t + (size_t)a * NDIM)
        : (false_t + ((size_t)b * FTN + (a - BS)) * NDIM);
    const float4* tp = (const float4*)tbase;

    float4 x0 = ldcs4(ip + lane);
    float4 x1 = ldcs4(ip + lane + 32);
    float4 x2 = ldcs4(ip + lane + 64);
    float4 x3 = ldcs4(ip + lane + 96);
    float4 t0 = ldnc4(tp + lane);
    float4 t1 = ldnc4(tp + lane + 32);
    float4 t2 = ldnc4(tp + lane + 64);
    float4 t3 = ldnc4(tp + lane + 96);

    float dot = 0.f, in2 = 0.f, tn2 = 0.f;
    acc3(x0, t0, dot, in2, tn2);
    acc3(x1, t1, dot, in2, tn2);
    acc3(x2, t2, dot, in2, tn2);
    acc3(x3, t3, dot, in2, tn2);

    #pragma unroll
    for (int o = 16; o > 0; o >>= 1) {
        dot += __shfl_xor_sync(0xffffffffu, dot, o);
        in2 += __shfl_xor_sync(0xffffffffu, in2, o);
        tn2 += __shfl_xor_sync(0xffffffffu, tn2, o);
    }
    if (lane == 0) {
        float scale = expf(logit_scale[0]);
        float lg = scale * dot * rsqrtf(in2 * tn2);   // |lg| <= scale (= e)
        float e  = expf(lg);
        g_exp[gwarp] = e;
        if (a < BS) g_expT[(size_t)a * BS + b] = e;
        if (a == b) g_diagL[b] = lg;
    }

#if __CUDA_ARCH__ >= 900
    cudaTriggerProgrammaticLaunchCompletion();
#endif
}

// ---------------------------------------------------------------------------
// Kernel 2 (PDL secondary): launches overlapped with kernel 1; waits for the
// primary grid's memory via cudaGridDependencySynchronize, then: one warp per
// CE term, sum + log only, one atomicAdd per block.
// ---------------------------------------------------------------------------
__global__ __launch_bounds__(256) void cl_lse_kernel(float* __restrict__ out)
{
#if __CUDA_ARCH__ >= 900
    cudaGridDependencySynchronize();
#endif

    __shared__ float s_term[8];
    int gw   = (blockIdx.x * blockDim.x + threadIdx.x) >> 5;
    int wid  = threadIdx.x >> 5;
    int lane = threadIdx.x & 31;

    float s = 0.f;
    float diag;
    if (gw < BS) {
        const float* row = g_exp + (size_t)gw * ATN;
        #pragma unroll
        for (int i = 0; i < 8; i++) s += row[lane + 32 * i];
        if (lane < FTN) s += row[BS + lane];
        diag = g_diagL[gw];
    } else {
        int a = gw - BS;
        const float* row = g_expT + (size_t)a * BS;
        #pragma unroll
        for (int i = 0; i < 8; i++) s += row[lane + 32 * i];
        diag = g_diagL[a];
    }

    #pragma unroll
    for (int o = 16; o > 0; o >>= 1)
        s += __shfl_xor_sync(0xffffffffu, s, o);

    if (lane == 0)
        s_term[wid] = logf(s) - diag;
    __syncthreads();

    if (wid == 0) {
        float t = (lane < 8) ? s_term[lane] : 0.f;
        #pragma unroll
        for (int o = 4; o > 0; o >>= 1)
            t += __shfl_xor_sync(0xffffffffu, t, o);
        if (lane == 0)
            atomicAdd(out, t * (1.0f / (2.0f * BS)));
    }
}

extern "C" void kernel_launch(void* const* d_in, const int* in_sizes, int n_in,
                              void* d_out, int out_size)
{
    const float* img     = (const float*)d_in[0];  // [256, 264, 512]
    const float* rand_t  = (const float*)d_in[1];  // [256, 512]
    const float* false_t = (const float*)d_in[2];  // [2048, 512]
    const float* lscale  = (const float*)d_in[3];  // [1]
    float* out = (float*)d_out;

    const int nwarps1 = BS * ATN;                   // 67584
    const int tpb = 256;
    const int nblocks1 = nwarps1 * 32 / tpb;        // 8448 (exact)

    cl_dot_kernel<<<nblocks1, tpb>>>(img, rand_t, false_t, lscale, out);

    // Secondary with programmatic (overlapped) dependent launch.
    cudaLaunchConfig_t cfg = {};
    cfg.gridDim  = dim3(64, 1, 1);
    cfg.blockDim = dim3(tpb, 1, 1);
    cfg.dynamicSmemBytes = 0;
    cfg.stream = 0;   // same (capture) stream as the <<<>>> launch above
    cudaLaunchAttribute attrs[1];
    attrs[0].id = cudaLaunchAttributeProgrammaticStreamSerialization;
    attrs[0].val.programmaticStreamSerializationAllowed = 1;
    cfg.attrs = attrs;
    cfg.numAttrs = 1;
    cudaLaunchKernelEx(&cfg, cl_lse_kernel, out);
}